// round 1
// baseline (speedup 1.0000x reference)
#include <cuda_runtime.h>

// 5x5 box-filter mean with reflect padding, NCHW fp32, H=W=512.
// Separable in shared memory: load halo tile -> horizontal 5-sum -> vertical
// 5-sum -> *(1/25) -> coalesced store.

#define IMG_H 512
#define IMG_W 512
#define PADR  2
#define TW    128   // output tile width
#define TH    16    // output tile height
#define INW   (TW + 2*PADR)  // 132
#define INH   (TH + 2*PADR)  // 20
#define NTHREADS 256

__global__ __launch_bounds__(NTHREADS)
void box5_kernel(const float* __restrict__ in, float* __restrict__ out)
{
    __shared__ float raw[INH][INW];   // 20*132*4 = 10560 B
    __shared__ float hs[INH][TW];     // 20*128*4 = 10240 B

    const int tile_x = blockIdx.x * TW;
    const int tile_y = blockIdx.y * TH;
    const float* __restrict__ img  = in  + (size_t)blockIdx.z * (IMG_H * IMG_W);
    float* __restrict__       oimg = out + (size_t)blockIdx.z * (IMG_H * IMG_W);

    const int tid = threadIdx.x;

    // ---- Load input tile + halo with reflect indexing ----
    #pragma unroll
    for (int i = tid; i < INH * INW; i += NTHREADS) {
        const int r = i / INW;
        const int c = i - r * INW;
        int gy = tile_y + r - PADR;
        int gx = tile_x + c - PADR;
        // reflect (no edge repeat): -k -> k ; (N-1)+k -> (N-1)-k
        gy = (gy < 0) ? -gy : ((gy >= IMG_H) ? (2 * IMG_H - 2 - gy) : gy);
        gx = (gx < 0) ? -gx : ((gx >= IMG_W) ? (2 * IMG_W - 2 - gx) : gx);
        raw[r][c] = img[gy * IMG_W + gx];
    }
    __syncthreads();

    // ---- Horizontal 5-tap sums ----
    #pragma unroll
    for (int i = tid; i < INH * TW; i += NTHREADS) {
        const int r = i / TW;
        const int c = i - r * TW;
        hs[r][c] = raw[r][c] + raw[r][c + 1] + raw[r][c + 2]
                 + raw[r][c + 3] + raw[r][c + 4];
    }
    __syncthreads();

    // ---- Vertical 5-tap sums + scale + store ----
    const float inv25 = 1.0f / 25.0f;
    #pragma unroll
    for (int i = tid; i < TH * TW; i += NTHREADS) {
        const int r = i / TW;
        const int c = i - r * TW;
        const float s = hs[r][c] + hs[r + 1][c] + hs[r + 2][c]
                      + hs[r + 3][c] + hs[r + 4][c];
        oimg[(tile_y + r) * IMG_W + (tile_x + c)] = s * inv25;
    }
}

extern "C" void kernel_launch(void* const* d_in, const int* in_sizes, int n_in,
                              void* d_out, int out_size)
{
    const float* in = (const float*)d_in[0];
    float* out = (float*)d_out;

    const int planes = in_sizes[0] / (IMG_H * IMG_W);  // 32*3 = 96

    dim3 grid(IMG_W / TW, IMG_H / TH, planes);  // (4, 32, 96)
    dim3 block(NTHREADS);
    box5_kernel<<<grid, block>>>(in, out);
}

// round 2
// speedup vs baseline: 1.2582x; 1.2582x over previous
#include <cuda_runtime.h>

// 5x5 box-filter mean, reflect padding, NCHW fp32, H=W=512.
// Fully vectorized (float4) separable filter:
//   smem raw tile (w/ halo) -> per-thread horizontal 5-sums in registers ->
//   running vertical window -> STG.128.

#define IMG    512
#define TW     128            // output tile width (floats)
#define TH     32             // output tile height
#define TVW    (TW / 4)       // 32 float4 per row (center)
#define ROWS   (TH + 4)       // 36 input rows
#define LPAD   4              // left pad floats (keeps center 16B-aligned)
#define ROWF   (LPAD + TW + 4) // 136 floats per smem row

__global__ __launch_bounds__(256)
void box5_kernel(const float* __restrict__ in, float* __restrict__ out)
{
    __shared__ float raw[ROWS][ROWF];   // 36*136*4 = 19584 B

    const int tx  = threadIdx.x;        // 0..31  -> float4 column
    const int ty  = threadIdx.y;        // 0..7   -> row group
    const int tid = ty * 32 + tx;

    const int tile_x = blockIdx.x * TW;
    const int tile_y = blockIdx.y * TH;
    const float* __restrict__ img  = in  + (size_t)blockIdx.z * (IMG * IMG);
    float* __restrict__       oimg = out + (size_t)blockIdx.z * (IMG * IMG);

    // ---- Phase 1a: vectorized center loads (36 rows x 32 float4) ----
    #pragma unroll
    for (int v = tid; v < ROWS * TVW; v += 256) {
        const int r = v >> 5;           // v / 32
        const int c = v & 31;           // v % 32
        int gy = tile_y + r - 2;
        gy = (gy < 0) ? -gy : ((gy >= IMG) ? (2 * IMG - 2 - gy) : gy);
        const float4 val =
            *reinterpret_cast<const float4*>(img + gy * IMG + tile_x + c * 4);
        *reinterpret_cast<float4*>(&raw[r][LPAD + c * 4]) = val;
    }

    // ---- Phase 1b: scalar halo loads (36 rows x 4 floats) ----
    if (tid < ROWS * 4) {
        const int r = tid >> 2;
        const int w = tid & 3;
        int gy = tile_y + r - 2;
        gy = (gy < 0) ? -gy : ((gy >= IMG) ? (2 * IMG - 2 - gy) : gy);
        int gx, sc;
        if (w < 2) { gx = tile_x - 2 + w;        sc = 2 + w; }
        else       { gx = tile_x + TW + (w - 2); sc = LPAD + TW + (w - 2); }
        gx = (gx < 0) ? -gx : ((gx >= IMG) ? (2 * IMG - 2 - gx) : gx);
        raw[r][sc] = img[gy * IMG + gx];
    }
    __syncthreads();

    // ---- Phase 2: horizontal 5-sums in registers for 8 input rows ----
    const int rbase = ty * 4;           // first output row of this thread
    float4 h[8];
    #pragma unroll
    for (int k = 0; k < 8; k++) {
        const float* rp = &raw[rbase + k][tx * 4];
        const float4 l = *reinterpret_cast<const float4*>(rp);      // cols -4..-1
        const float4 c = *reinterpret_cast<const float4*>(rp + 4);  // cols  0..3
        const float4 r = *reinterpret_cast<const float4*>(rp + 8);  // cols  4..7
        const float s = c.x + c.y + c.z + c.w;
        h[k].x = (s - c.w) + l.z + l.w;   // x[-2..2]
        h[k].y = s + l.w;                 // x[-1..3]
        h[k].z = s + r.x;                 // x[ 0..4]
        h[k].w = (s - c.x) + r.x + r.y;   // x[ 1..5]
    }

    // ---- Phase 3: running vertical 5-window + scale + STG.128 ----
    const float inv25 = 1.0f / 25.0f;
    float4 v;
    v.x = h[0].x + h[1].x + h[2].x + h[3].x + h[4].x;
    v.y = h[0].y + h[1].y + h[2].y + h[3].y + h[4].y;
    v.z = h[0].z + h[1].z + h[2].z + h[3].z + h[4].z;
    v.w = h[0].w + h[1].w + h[2].w + h[3].w + h[4].w;

    float* obase = oimg + (tile_y + rbase) * IMG + tile_x + tx * 4;

    float4 o;
    o.x = v.x * inv25; o.y = v.y * inv25; o.z = v.z * inv25; o.w = v.w * inv25;
    *reinterpret_cast<float4*>(obase) = o;

    #pragma unroll
    for (int k = 1; k < 4; k++) {
        v.x = v.x - h[k - 1].x + h[k + 4].x;
        v.y = v.y - h[k - 1].y + h[k + 4].y;
        v.z = v.z - h[k - 1].z + h[k + 4].z;
        v.w = v.w - h[k - 1].w + h[k + 4].w;
        o.x = v.x * inv25; o.y = v.y * inv25; o.z = v.z * inv25; o.w = v.w * inv25;
        *reinterpret_cast<float4*>(obase + k * IMG) = o;
    }
}

extern "C" void kernel_launch(void* const* d_in, const int* in_sizes, int n_in,
                              void* d_out, int out_size)
{
    const float* in = (const float*)d_in[0];
    float* out = (float*)d_out;

    const int planes = in_sizes[0] / (IMG * IMG);   // 96

    dim3 grid(IMG / TW, IMG / TH, planes);          // (4, 16, 96)
    dim3 block(32, 8);
    box5_kernel<<<grid, block>>>(in, out);
}